// round 11
// baseline (speedup 1.0000x reference)
#include <cuda_runtime.h>
#include <cuda_fp16.h>
#include <cstdint>

#define DM   1024
#define NH   16
#define DKH  64
#define BB   4
#define TS   2048
#define MTOT (BB*TS)        // 8192
#define ELEMS (MTOT*DM)     // 8388608

// Scratch (static device memory — no allocation allowed)
__device__ __half g_q[ELEMS];          // [B,H,T,dk] fp16, pre-scaled
__device__ __half g_k[ELEMS];          // [B,H,T,dk] fp16
__device__ __half g_v[ELEMS];          // [B,H,dk,T] fp16 (transposed per head)
__device__ __half g_y[ELEMS];          // [B,T,C] fp16
__device__ __half g_xh[ELEMS];         // x  -> fp16
__device__ __half g_wah[3 * DM * DM];  // w_attn -> fp16
__device__ __half g_wph[DM * DM];      // w_proj -> fp16

__device__ __forceinline__ void mma16(float* d, const unsigned* a,
                                      unsigned b0, unsigned b1) {
    asm volatile(
        "mma.sync.aligned.m16n8k16.row.col.f32.f16.f16.f32 "
        "{%0,%1,%2,%3}, {%4,%5,%6,%7}, {%8,%9}, {%0,%1,%2,%3};\n"
        : "+f"(d[0]), "+f"(d[1]), "+f"(d[2]), "+f"(d[3])
        : "r"(a[0]), "r"(a[1]), "r"(a[2]), "r"(a[3]), "r"(b0), "r"(b1));
}

// ldmatrix x4: m0..m3 -> r0..r3; lanes 0-7/8-15/16-23/24-31 address m0..m3 rows
__device__ __forceinline__ void ldsm4(unsigned* r, unsigned saddr) {
    asm volatile("ldmatrix.sync.aligned.m8n8.x4.shared.b16 {%0,%1,%2,%3}, [%4];"
                 : "=r"(r[0]), "=r"(r[1]), "=r"(r[2]), "=r"(r[3]) : "r"(saddr));
}

__device__ __forceinline__ void cpa16(void* smem, const void* g) {
    unsigned s = (unsigned)__cvta_generic_to_shared(smem);
    asm volatile("cp.async.cg.shared.global [%0], [%1], 16;" :: "r"(s), "l"(g));
}
__device__ __forceinline__ void cpa_commit() {
    asm volatile("cp.async.commit_group;");
}
template <int N>
__device__ __forceinline__ void cpa_wait() {
    asm volatile("cp.async.wait_group %0;" :: "n"(N));
}

// fp32 -> fp16 (RN) bulk convert
__global__ void f2h(const float2* __restrict__ s, __half2* __restrict__ d, int n2) {
    int i = blockIdx.x * blockDim.x + threadIdx.x;
    if (i < n2) { float2 v = s[i]; d[i] = __floats2half2_rn(v.x, v.y); }
}

// ---------------------------------------------------------------------------
// fp16 GEMM: C[M,N] = A[M,K] @ B[N,K]^T + bias (A,B fp16; accum fp32).
// BM=BN=128, BK=32 (2 k16 planes); 128 threads = 4 warps, warp tile 64x64.
// 3-stage 16B-cp.async ring; ldmatrix.x4 fragment loads (8 LDSM/plane/warp).
// smem plane rows: 8 data u32 + 4 pad (stride 12) -> LDSM conflict-free.
// MODE 0: fp32 row-major + bias.  MODE 1: fp16 q/k [B,H,T,64] (Q*0.125) and
// v transposed [B,H,64,T].
// ---------------------------------------------------------------------------
#define PLANE  1536                   // 128 rows * 12 u32
#define STAGEU (4 * PLANE)            // A(2 planes) + B(2 planes)
#define GSTG   3
#define GEMM_SMEM (GSTG * STAGEU * 4) // 73728 B

template <int MODE>
__global__ void __launch_bounds__(128, 2) gemm_h(
    const __half* __restrict__ A, const __half* __restrict__ Bm,
    const float* __restrict__ bias, float* __restrict__ C,
    __half* __restrict__ qb, __half* __restrict__ kb, __half* __restrict__ vb,
    int M, int N, int K)
{
    extern __shared__ unsigned smu[];

    const int tid  = threadIdx.x;
    const int lane = tid & 31;
    const int warp = tid >> 5;
    const int wm = warp >> 1, wn = warp & 1;
    const int bm = blockIdx.y * 128;
    const int bn = blockIdx.x * 128;
    const int NT = K >> 5;

    float acc[4][8][4];
#pragma unroll
    for (int mi = 0; mi < 4; mi++)
#pragma unroll
        for (int ni = 0; ni < 8; ni++)
#pragma unroll
            for (int q = 0; q < 4; q++) acc[mi][ni][q] = 0.0f;

    // ldmatrix per-lane address components
    const int lrow = lane & 15, lcol = lane >> 4;
    const unsigned sbase = (unsigned)__cvta_generic_to_shared(smu);
    const unsigned aoff4 = 4u * ((unsigned)((wm * 64 + lrow) * 12 + lcol * 4));
    const unsigned boff4 = 4u * ((unsigned)((wn * 64 + lrow) * 12 + lcol * 4));

    // stage loader: 512 16B-chunks each for A and B, 8 cp.async per thread
    auto load_stage = [&](int t, int p) {
        const __half* Ag = A + (size_t)bm * K + t * 32;
        const __half* Bg = Bm + (size_t)bn * K + t * 32;
        unsigned base = p * STAGEU;
#pragma unroll
        for (int i = 0; i < 4; i++) {
            int idx = i * 128 + tid;        // 0..511
            int r = idx >> 2, ch = idx & 3;
            int pl = ch >> 1, c4 = (ch & 1) * 4;
            cpa16(&smu[base + pl * PLANE + r * 12 + c4],
                  Ag + (size_t)r * K + pl * 16 + c4 * 2);
            cpa16(&smu[base + 2 * PLANE + pl * PLANE + r * 12 + c4],
                  Bg + (size_t)r * K + pl * 16 + c4 * 2);
        }
        cpa_commit();
    };

    load_stage(0, 0); load_stage(1, 1); load_stage(2, 2);

    for (int t = 0; t < NT; t++) {
        const int p = t % 3;
        cpa_wait<2>();
        __syncthreads();
        const unsigned stg = sbase + 4u * (unsigned)(p * STAGEU);

#pragma unroll
        for (int pl = 0; pl < 2; pl++) {
            const unsigned apl = stg + 4u * (unsigned)(pl * PLANE) + aoff4;
            const unsigned bpl = stg + 4u * (unsigned)((2 + pl) * PLANE) + boff4;
            unsigned a[4][4], bf[4][4];
#pragma unroll
            for (int mi = 0; mi < 4; mi++)
                ldsm4(a[mi], apl + (unsigned)(mi * 16 * 12 * 4));
#pragma unroll
            for (int np = 0; np < 4; np++)
                ldsm4(bf[np], bpl + (unsigned)(np * 16 * 12 * 4));
#pragma unroll
            for (int mi = 0; mi < 4; mi++)
#pragma unroll
                for (int np = 0; np < 4; np++) {
                    mma16(acc[mi][2 * np],     a[mi], bf[np][0], bf[np][2]);
                    mma16(acc[mi][2 * np + 1], a[mi], bf[np][1], bf[np][3]);
                }
        }
        __syncthreads();
        if (t + 3 < NT) load_stage(t + 3, p);
    }

    // Epilogue
#pragma unroll
    for (int mi = 0; mi < 4; mi++) {
#pragma unroll
        for (int ni = 0; ni < 8; ni++) {
            int row = bm + wm * 64 + mi * 16 + (lane >> 2);
            int col = bn + wn * 64 + ni * 8 + 2 * (lane & 3);
#pragma unroll
            for (int hf = 0; hf < 2; hf++) {
                int r = row + hf * 8;
                float v0 = acc[mi][ni][hf * 2 + 0] + bias[col];
                float v1 = acc[mi][ni][hf * 2 + 1] + bias[col + 1];
                if (MODE == 0) {
                    *(float2*)(C + (size_t)r * N + col) = make_float2(v0, v1);
                } else {
                    int which = col >> 10;          // 0=q,1=k,2=v
                    int cc = col & 1023;
                    int hh = cc >> 6, dd = cc & 63;
                    int bi = r >> 11, tt = r & 2047;
                    if (which == 0) { v0 *= 0.125f; v1 *= 0.125f; }  // 1/sqrt(64)
                    if (which == 2) {
                        // transposed: [B,H,dk,T]
                        size_t off = (((size_t)bi * NH + hh) * DKH + dd) * TS + tt;
                        vb[off]      = __float2half_rn(v0);
                        vb[off + TS] = __float2half_rn(v1);
                    } else {
                        __half* dst = (which == 0) ? qb : kb;
                        size_t off = (((size_t)bi * NH + hh) * TS + tt) * DKH + dd;
                        *(__half2*)(dst + off) = __floats2half2_rn(v0, v1);
                    }
                }
            }
        }
    }
}

// ---------------------------------------------------------------------------
// Flash attention (fp16 operands, fp32 accum): block = 128 q-rows x (head,
// batch), 256 threads (8 warps x 16 q-rows). K/V tiles of 64 keys, double-
// buffered 16B cp.async; ldmatrix.x4 fragment loads for Q/K/P/V.
// smem rows: 32 data u32 + 4 pad (stride 36) -> LDSM conflict-free.
// V pre-transposed in gmem ([B,H,dk,T]).
// ---------------------------------------------------------------------------
#define AST   36
#define KBUFU (64 * AST)
#define ATTN_SMEM ((2 * 128 * AST + 4 * KBUFU) * 4)   // 73728 B

__global__ void __launch_bounds__(256, 1) attn_kernel(
    const __half* __restrict__ qg, const __half* __restrict__ kg,
    const __half* __restrict__ vg, __half* __restrict__ yg)
{
    extern __shared__ unsigned su[];
    unsigned* Qs = su;                  // 128*36
    unsigned* Ss = Qs + 128 * AST;      // 128*36
    unsigned* Ks = Ss + 128 * AST;      // 2 x 64*36
    unsigned* Vt = Ks + 2 * KBUFU;      // 2 x 64*36

    const int tid  = threadIdx.x;
    const int lane = tid & 31;
    const int warp = tid >> 5;
    const int qt = blockIdx.x, h = blockIdx.y, b = blockIdx.z;
    const size_t hb = ((size_t)b * NH + h) * TS * DKH;
    const int mb = warp * 16;
    const int c = lane & 3, lr = lane >> 2;
    const int r = mb + lr;

    // ldmatrix per-lane address components
    const int lrow = lane & 15, lcol = lane >> 4;
    const unsigned sb = (unsigned)__cvta_generic_to_shared(su);
    const unsigned qfrag = sb + 4u * (unsigned)((mb + lrow) * AST + lcol * 4);
    const unsigned sfrag = sb + 4u * (unsigned)(128 * AST + (mb + lrow) * AST + lcol * 4);
    const unsigned kvoff = 4u * (unsigned)(lrow * AST + lcol * 4);
    const unsigned kbase = sb + 4u * (unsigned)(2 * 128 * AST);
    const unsigned vbase = sb + 4u * (unsigned)(2 * 128 * AST + 2 * KBUFU);

    // Q tile 128x64 fp16: 1024 16B chunks, 4/thread
    {
        const __half* qp = qg + hb + (size_t)qt * 128 * DKH;
#pragma unroll
        for (int i = 0; i < 4; i++) {
            int idx = i * 256 + tid;
            int rr = idx >> 3, ch = idx & 7;
            cpa16(&Qs[rr * AST + ch * 4], qp + rr * 64 + ch * 8);
        }
    }

    auto load_kv = [&](int j, int buf) {
        const __half* kp = kg + hb + (size_t)j * 64 * DKH;
        const __half* vp = vg + hb + (size_t)j * 64;     // transposed rows: +d*TS
#pragma unroll
        for (int i = 0; i < 2; i++) {
            int idx = i * 256 + tid;        // 0..511
            int rr = idx >> 3, ch = idx & 7;
            cpa16(&Ks[buf * KBUFU + rr * AST + ch * 4], kp + rr * 64 + ch * 8);
            cpa16(&Vt[buf * KBUFU + rr * AST + ch * 4], vp + (size_t)rr * TS + ch * 8);
        }
    };

    load_kv(0, 0);
    cpa_commit();       // group: Q + KV0

    float accO[8][4];
#pragma unroll
    for (int nf = 0; nf < 8; nf++)
#pragma unroll
        for (int q = 0; q < 4; q++) accO[nf][q] = 0.0f;
    float mrow[2] = {-1e30f, -1e30f};
    float lrow2[2] = {0.0f, 0.0f};

    for (int j = 0; j < TS / 64; j++) {
        int buf = j & 1;
        if (j + 1 < TS / 64) load_kv(j + 1, buf ^ 1);
        cpa_commit();
        cpa_wait<1>();
        __syncthreads();   // tile j (and Q on j=0) resident

        const unsigned kf = kbase + 4u * (unsigned)(buf * KBUFU) + kvoff;
        const unsigned vf = vbase + 4u * (unsigned)(buf * KBUFU) + kvoff;

        // S = Q @ K^T  (16 q-rows x 64 keys per warp), dim in 4 k16 chunks
        float accS[8][4];
#pragma unroll
        for (int nf = 0; nf < 8; nf++)
#pragma unroll
            for (int q = 0; q < 4; q++) accS[nf][q] = 0.0f;

#pragma unroll
        for (int c16 = 0; c16 < 4; c16++) {
            const unsigned cu4 = 4u * (unsigned)(c16 * 8);
            unsigned a[4];
            ldsm4(a, qfrag + cu4);
#pragma unroll
            for (int np = 0; np < 4; np++) {
                unsigned kk[4];
                ldsm4(kk, kf + 4u * (unsigned)(np * 16 * AST) + cu4);
                mma16(accS[2 * np],     a, kk[0], kk[2]);
                mma16(accS[2 * np + 1], a, kk[1], kk[3]);
            }
        }

        // Online softmax (2 rows/thread: r, r+8)
        float tm0 = -1e30f, tm1 = -1e30f;
#pragma unroll
        for (int nf = 0; nf < 8; nf++) {
            tm0 = fmaxf(tm0, fmaxf(accS[nf][0], accS[nf][1]));
            tm1 = fmaxf(tm1, fmaxf(accS[nf][2], accS[nf][3]));
        }
        tm0 = fmaxf(tm0, __shfl_xor_sync(0xffffffffu, tm0, 1));
        tm0 = fmaxf(tm0, __shfl_xor_sync(0xffffffffu, tm0, 2));
        tm1 = fmaxf(tm1, __shfl_xor_sync(0xffffffffu, tm1, 1));
        tm1 = fmaxf(tm1, __shfl_xor_sync(0xffffffffu, tm1, 2));

        float mn0 = fmaxf(mrow[0], tm0), mn1 = fmaxf(mrow[1], tm1);
        float al0 = __expf(mrow[0] - mn0), al1 = __expf(mrow[1] - mn1);

        float s0 = 0.0f, s1 = 0.0f;
#pragma unroll
        for (int nf = 0; nf < 8; nf++) {
            accS[nf][0] = __expf(accS[nf][0] - mn0);
            accS[nf][1] = __expf(accS[nf][1] - mn0);
            accS[nf][2] = __expf(accS[nf][2] - mn1);
            accS[nf][3] = __expf(accS[nf][3] - mn1);
            s0 += accS[nf][0] + accS[nf][1];
            s1 += accS[nf][2] + accS[nf][3];
        }
        s0 += __shfl_xor_sync(0xffffffffu, s0, 1);
        s0 += __shfl_xor_sync(0xffffffffu, s0, 2);
        s1 += __shfl_xor_sync(0xffffffffu, s1, 1);
        s1 += __shfl_xor_sync(0xffffffffu, s1, 2);

        lrow2[0] = lrow2[0] * al0 + s0;
        lrow2[1] = lrow2[1] * al1 + s1;
        mrow[0] = mn0; mrow[1] = mn1;

#pragma unroll
        for (int nf = 0; nf < 8; nf++) {
            accO[nf][0] *= al0; accO[nf][1] *= al0;
            accO[nf][2] *= al1; accO[nf][3] *= al1;
        }

        // P -> fp16, warp-private rows of Ss
#pragma unroll
        for (int nf = 0; nf < 8; nf++) {
            __half2 p0 = __floats2half2_rn(accS[nf][0], accS[nf][1]);
            __half2 p1 = __floats2half2_rn(accS[nf][2], accS[nf][3]);
            Ss[r * AST + nf * 4 + c]       = *(unsigned*)&p0;
            Ss[(r + 8) * AST + nf * 4 + c] = *(unsigned*)&p1;
        }
        __syncwarp();  // warp-local P round-trip only

        // O += P @ V   (keys in 4 k16 chunks; Vt rows = dims)
#pragma unroll
        for (int k16 = 0; k16 < 4; k16++) {
            const unsigned ku4 = 4u * (unsigned)(k16 * 8);
            unsigned a[4];
            ldsm4(a, sfrag + ku4);
#pragma unroll
            for (int np = 0; np < 4; np++) {
                unsigned vv[4];
                ldsm4(vv, vf + 4u * (unsigned)(np * 16 * AST) + ku4);
                mma16(accO[2 * np],     a, vv[0], vv[2]);
                mma16(accO[2 * np + 1], a, vv[1], vv[3]);
            }
        }
        __syncthreads();  // all warps done with buf before its next overwrite
    }

    // Normalize, write y fp16 [B,T,C]
    float inv0 = 1.0f / lrow2[0], inv1 = 1.0f / lrow2[1];
    size_t t0 = (size_t)b * TS + (size_t)qt * 128 + r;
#pragma unroll
    for (int nf = 0; nf < 8; nf++) {
        int c0 = nf * 8 + 2 * (lane & 3);
        *(__half2*)(yg + t0 * DM + h * 64 + c0) =
            __floats2half2_rn(accO[nf][0] * inv0, accO[nf][1] * inv0);
        *(__half2*)(yg + (t0 + 8) * DM + h * 64 + c0) =
            __floats2half2_rn(accO[nf][2] * inv1, accO[nf][3] * inv1);
    }
}

// ---------------------------------------------------------------------------
extern "C" void kernel_launch(void* const* d_in, const int* in_sizes, int n_in,
                              void* d_out, int out_size) {
    const float* x      = (const float*)d_in[0];
    const float* w_attn = (const float*)d_in[1];
    const float* b_attn = (const float*)d_in[2];
    const float* w_proj = (const float*)d_in[3];
    const float* b_proj = (const float*)d_in[4];
    float* out = (float*)d_out;

    __half *qp, *kp, *vp, *yp, *xh, *wah, *wph;
    cudaGetSymbolAddress((void**)&qp, g_q);
    cudaGetSymbolAddress((void**)&kp, g_k);
    cudaGetSymbolAddress((void**)&vp, g_v);
    cudaGetSymbolAddress((void**)&yp, g_y);
    cudaGetSymbolAddress((void**)&xh, g_xh);
    cudaGetSymbolAddress((void**)&wah, g_wah);
    cudaGetSymbolAddress((void**)&wph, g_wph);

    cudaFuncSetAttribute(gemm_h<1>, cudaFuncAttributeMaxDynamicSharedMemorySize,
                         GEMM_SMEM);
    cudaFuncSetAttribute(gemm_h<0>, cudaFuncAttributeMaxDynamicSharedMemorySize,
                         GEMM_SMEM);
    cudaFuncSetAttribute(attn_kernel, cudaFuncAttributeMaxDynamicSharedMemorySize,
                         ATTN_SMEM);

    // 0) convert inputs to fp16 (RN)
    f2h<<<ELEMS / 2 / 256, 256>>>((const float2*)x, (__half2*)xh, ELEMS / 2);
    f2h<<<3 * DM * DM / 2 / 256, 256>>>((const float2*)w_attn, (__half2*)wah,
                                        3 * DM * DM / 2);
    f2h<<<DM * DM / 2 / 256, 256>>>((const float2*)w_proj, (__half2*)wph,
                                    DM * DM / 2);

    // 1) QKV projection -> q/k [B,H,T,dk] (Q pre-scaled), v [B,H,dk,T]
    gemm_h<1><<<dim3(3 * DM / 128, MTOT / 128), 128, GEMM_SMEM>>>(
        xh, wah, b_attn, nullptr, qp, kp, vp, MTOT, 3 * DM, DM);

    // 2) Flash attention -> y fp16 [B,T,C]
    attn_kernel<<<dim3(TS / 128, NH, BB), 256, ATTN_SMEM>>>(qp, kp, vp, yp);

    // 3) Output projection -> d_out (fp32 + bias)
    gemm_h<0><<<dim3(DM / 128, MTOT / 128), 128, GEMM_SMEM>>>(
        yp, wph, b_proj, out, nullptr, nullptr, nullptr, MTOT, DM, DM);
}

// round 13
// speedup vs baseline: 1.0179x; 1.0179x over previous
#include <cuda_runtime.h>
#include <cuda_fp16.h>
#include <cstdint>

#define DM   1024
#define NH   16
#define DKH  64
#define BB   4
#define TS   2048
#define MTOT (BB*TS)        // 8192
#define ELEMS (MTOT*DM)     // 8388608

// Scratch (static device memory — no allocation allowed)
__device__ __half g_q[ELEMS];          // [B,H,T,dk] fp16, pre-scaled
__device__ __half g_k[ELEMS];          // [B,H,T,dk] fp16
__device__ __half g_v[ELEMS];          // [B,H,dk,T] fp16 (transposed per head)
__device__ __half g_y[ELEMS];          // [B,T,C] fp16
__device__ __half g_xh[ELEMS];         // x  -> fp16
__device__ __half g_wah[3 * DM * DM];  // w_attn -> fp16
__device__ __half g_wph[DM * DM];      // w_proj -> fp16

__device__ __forceinline__ void mma16(float* d, const unsigned* a,
                                      unsigned b0, unsigned b1) {
    asm volatile(
        "mma.sync.aligned.m16n8k16.row.col.f32.f16.f16.f32 "
        "{%0,%1,%2,%3}, {%4,%5,%6,%7}, {%8,%9}, {%0,%1,%2,%3};\n"
        : "+f"(d[0]), "+f"(d[1]), "+f"(d[2]), "+f"(d[3])
        : "r"(a[0]), "r"(a[1]), "r"(a[2]), "r"(a[3]), "r"(b0), "r"(b1));
}

__device__ __forceinline__ void cpa16(void* smem, const void* g) {
    unsigned s = (unsigned)__cvta_generic_to_shared(smem);
    asm volatile("cp.async.cg.shared.global [%0], [%1], 16;" :: "r"(s), "l"(g));
}
__device__ __forceinline__ void cpa_commit() {
    asm volatile("cp.async.commit_group;");
}
template <int N>
__device__ __forceinline__ void cpa_wait() {
    asm volatile("cp.async.wait_group %0;" :: "n"(N));
}

// fp32 -> fp16 (RN) bulk convert
__global__ void f2h(const float2* __restrict__ s, __half2* __restrict__ d, int n2) {
    int i = blockIdx.x * blockDim.x + threadIdx.x;
    if (i < n2) { float2 v = s[i]; d[i] = __floats2half2_rn(v.x, v.y); }
}

// ---------------------------------------------------------------------------
// fp16 GEMM: C[M,N] = A[M,K] @ B[N,K]^T + bias (A,B fp16; accum fp32).
// BM=BN=128, BK=32 (2 k16 planes); 256 threads = 8 warps, warp tile 64x32
// (2m x 4n). 3-stage 16B-cp.async ring; scalar-LDS fragment loads (stride-12
// u32 rows, bank-conflict-free). __launch_bounds__(256,2) -> 16 warps/SM.
// MODE 0: fp32 row-major + bias.  MODE 1: fp16 q/k [B,H,T,64] (Q*0.125) and
// v transposed [B,H,64,T].
// ---------------------------------------------------------------------------
#define PLANE  1536                   // 128 rows * 12 u32
#define STAGEU (4 * PLANE)            // A(2 planes) + B(2 planes)
#define GSTG   3
#define GEMM_SMEM (GSTG * STAGEU * 4) // 73728 B

template <int MODE>
__global__ void __launch_bounds__(256, 2) gemm_h(
    const __half* __restrict__ A, const __half* __restrict__ Bm,
    const float* __restrict__ bias, float* __restrict__ C,
    __half* __restrict__ qb, __half* __restrict__ kb, __half* __restrict__ vb,
    int M, int N, int K)
{
    extern __shared__ unsigned smu[];

    const int tid  = threadIdx.x;
    const int lane = tid & 31;
    const int warp = tid >> 5;
    const int wm = warp >> 2, wn = warp & 3;   // 2 x 4 warp grid
    const int bm = blockIdx.y * 128;
    const int bn = blockIdx.x * 128;
    const int NT = K >> 5;

    float acc[4][4][4];
#pragma unroll
    for (int mi = 0; mi < 4; mi++)
#pragma unroll
        for (int ni = 0; ni < 4; ni++)
#pragma unroll
            for (int q = 0; q < 4; q++) acc[mi][ni][q] = 0.0f;

    // stage loader: A 512 + B 512 16B-chunks, 4 cp.async per thread
    auto load_stage = [&](int t, int p) {
        const __half* Ag = A + (size_t)bm * K + t * 32;
        const __half* Bg = Bm + (size_t)bn * K + t * 32;
        unsigned base = p * STAGEU;
#pragma unroll
        for (int i = 0; i < 2; i++) {
            int idx = i * 256 + tid;        // 0..511
            int r = idx >> 2, ch = idx & 3;
            int pl = ch >> 1, c4 = (ch & 1) * 4;
            cpa16(&smu[base + pl * PLANE + r * 12 + c4],
                  Ag + (size_t)r * K + pl * 16 + c4 * 2);
            cpa16(&smu[base + 2 * PLANE + pl * PLANE + r * 12 + c4],
                  Bg + (size_t)r * K + pl * 16 + c4 * 2);
        }
        cpa_commit();
    };

    load_stage(0, 0); load_stage(1, 1); load_stage(2, 2);

    for (int t = 0; t < NT; t++) {
        const int p = t % 3;
        cpa_wait<2>();
        __syncthreads();
        const unsigned* Ab = smu + p * STAGEU;
        const unsigned* Bb = Ab + 2 * PLANE;
        const int c = lane & 3, lr = lane >> 2;

#pragma unroll
        for (int pl = 0; pl < 2; pl++) {
            const unsigned* Ap = Ab + pl * PLANE;
            const unsigned* Bp = Bb + pl * PLANE;
            unsigned a[4][4], b[4][2];
#pragma unroll
            for (int mi = 0; mi < 4; mi++) {
                int r = wm * 64 + mi * 16 + lr;
                a[mi][0] = Ap[r * 12 + c];
                a[mi][1] = Ap[(r + 8) * 12 + c];
                a[mi][2] = Ap[r * 12 + c + 4];
                a[mi][3] = Ap[(r + 8) * 12 + c + 4];
            }
#pragma unroll
            for (int ni = 0; ni < 4; ni++) {
                int rB = wn * 32 + ni * 8 + lr;
                b[ni][0] = Bp[rB * 12 + c];
                b[ni][1] = Bp[rB * 12 + c + 4];
            }
#pragma unroll
            for (int mi = 0; mi < 4; mi++)
#pragma unroll
                for (int ni = 0; ni < 4; ni++)
                    mma16(acc[mi][ni], a[mi], b[ni][0], b[ni][1]);
        }
        __syncthreads();
        if (t + 3 < NT) load_stage(t + 3, p);
    }

    // Epilogue
#pragma unroll
    for (int mi = 0; mi < 4; mi++) {
#pragma unroll
        for (int ni = 0; ni < 4; ni++) {
            int row = bm + wm * 64 + mi * 16 + (lane >> 2);
            int col = bn + wn * 32 + ni * 8 + 2 * (lane & 3);
#pragma unroll
            for (int hf = 0; hf < 2; hf++) {
                int r = row + hf * 8;
                float v0 = acc[mi][ni][hf * 2 + 0] + bias[col];
                float v1 = acc[mi][ni][hf * 2 + 1] + bias[col + 1];
                if (MODE == 0) {
                    *(float2*)(C + (size_t)r * N + col) = make_float2(v0, v1);
                } else {
                    int which = col >> 10;          // 0=q,1=k,2=v
                    int cc = col & 1023;
                    int hh = cc >> 6, dd = cc & 63;
                    int bi = r >> 11, tt = r & 2047;
                    if (which == 0) { v0 *= 0.125f; v1 *= 0.125f; }  // 1/sqrt(64)
                    if (which == 2) {
                        // transposed: [B,H,dk,T]
                        size_t off = (((size_t)bi * NH + hh) * DKH + dd) * TS + tt;
                        vb[off]      = __float2half_rn(v0);
                        vb[off + TS] = __float2half_rn(v1);
                    } else {
                        __half* dst = (which == 0) ? qb : kb;
                        size_t off = (((size_t)bi * NH + hh) * TS + tt) * DKH + dd;
                        *(__half2*)(dst + off) = __floats2half2_rn(v0, v1);
                    }
                }
            }
        }
    }
}

// ---------------------------------------------------------------------------
// Flash attention (fp16 operands, fp32 accum): block = 128 q-rows x (head,
// batch), 256 threads (8 warps x 16 q-rows). K/V tiles of 64 keys, double-
// buffered 16B cp.async; scalar-LDS fragment loads (stride-36 u32 rows,
// conflict-free). V pre-transposed in gmem. __launch_bounds__(256,2).
// ---------------------------------------------------------------------------
#define AST   36
#define KBUFU (64 * AST)
#define ATTN_SMEM ((2 * 128 * AST + 4 * KBUFU) * 4)   // 73728 B

__global__ void __launch_bounds__(256, 2) attn_kernel(
    const __half* __restrict__ qg, const __half* __restrict__ kg,
    const __half* __restrict__ vg, __half* __restrict__ yg)
{
    extern __shared__ unsigned su[];
    unsigned* Qs = su;                  // 128*36
    unsigned* Ss = Qs + 128 * AST;      // 128*36
    unsigned* Ks = Ss + 128 * AST;      // 2 x 64*36
    unsigned* Vt = Ks + 2 * KBUFU;      // 2 x 64*36

    const int tid  = threadIdx.x;
    const int lane = tid & 31;
    const int warp = tid >> 5;
    const int qt = blockIdx.x, h = blockIdx.y, b = blockIdx.z;
    const size_t hb = ((size_t)b * NH + h) * TS * DKH;
    const int mb = warp * 16;
    const int c = lane & 3, lr = lane >> 2;
    const int r = mb + lr;

    // Q tile 128x64 fp16: 1024 16B chunks, 4/thread
    {
        const __half* qp = qg + hb + (size_t)qt * 128 * DKH;
#pragma unroll
        for (int i = 0; i < 4; i++) {
            int idx = i * 256 + tid;
            int rr = idx >> 3, ch = idx & 7;
            cpa16(&Qs[rr * AST + ch * 4], qp + rr * 64 + ch * 8);
        }
    }

    auto load_kv = [&](int j, int buf) {
        const __half* kp = kg + hb + (size_t)j * 64 * DKH;
        const __half* vp = vg + hb + (size_t)j * 64;     // transposed rows: +d*TS
#pragma unroll
        for (int i = 0; i < 2; i++) {
            int idx = i * 256 + tid;        // 0..511
            int rr = idx >> 3, ch = idx & 7;
            cpa16(&Ks[buf * KBUFU + rr * AST + ch * 4], kp + rr * 64 + ch * 8);
            cpa16(&Vt[buf * KBUFU + rr * AST + ch * 4], vp + (size_t)rr * TS + ch * 8);
        }
    };

    load_kv(0, 0);
    cpa_commit();       // group: Q + KV0

    float accO[8][4];
#pragma unroll
    for (int nf = 0; nf < 8; nf++)
#pragma unroll
        for (int q = 0; q < 4; q++) accO[nf][q] = 0.0f;
    float mrow[2] = {-1e30f, -1e30f};
    float lrow[2] = {0.0f, 0.0f};

    for (int j = 0; j < TS / 64; j++) {
        int buf = j & 1;
        if (j + 1 < TS / 64) load_kv(j + 1, buf ^ 1);
        cpa_commit();
        cpa_wait<1>();
        __syncthreads();   // tile j (and Q on j=0) resident

        const unsigned* Kb = Ks + buf * KBUFU;
        const unsigned* Vb = Vt + buf * KBUFU;

        // S = Q @ K^T  (16 q-rows x 64 keys per warp), dim in 4 k16 chunks
        float accS[8][4];
#pragma unroll
        for (int nf = 0; nf < 8; nf++)
#pragma unroll
            for (int q = 0; q < 4; q++) accS[nf][q] = 0.0f;

#pragma unroll
        for (int c16 = 0; c16 < 4; c16++) {
            const int cu = c16 * 8;
            unsigned a[4];
            a[0] = Qs[r * AST + cu + c];
            a[1] = Qs[(r + 8) * AST + cu + c];
            a[2] = Qs[r * AST + cu + c + 4];
            a[3] = Qs[(r + 8) * AST + cu + c + 4];
#pragma unroll
            for (int nf = 0; nf < 8; nf++) {
                unsigned bf0, bf1;
                int kr = nf * 8 + lr;
                bf0 = Kb[kr * AST + cu + c];
                bf1 = Kb[kr * AST + cu + c + 4];
                mma16(accS[nf], a, bf0, bf1);
            }
        }

        // Online softmax (2 rows/thread: r, r+8)
        float tm0 = -1e30f, tm1 = -1e30f;
#pragma unroll
        for (int nf = 0; nf < 8; nf++) {
            tm0 = fmaxf(tm0, fmaxf(accS[nf][0], accS[nf][1]));
            tm1 = fmaxf(tm1, fmaxf(accS[nf][2], accS[nf][3]));
        }
        tm0 = fmaxf(tm0, __shfl_xor_sync(0xffffffffu, tm0, 1));
        tm0 = fmaxf(tm0, __shfl_xor_sync(0xffffffffu, tm0, 2));
        tm1 = fmaxf(tm1, __shfl_xor_sync(0xffffffffu, tm1, 1));
        tm1 = fmaxf(tm1, __shfl_xor_sync(0xffffffffu, tm1, 2));

        float mn0 = fmaxf(mrow[0], tm0), mn1 = fmaxf(mrow[1], tm1);
        float al0 = __expf(mrow[0] - mn0), al1 = __expf(mrow[1] - mn1);

        float s0 = 0.0f, s1 = 0.0f;
#pragma unroll
        for (int nf = 0; nf < 8; nf++) {
            accS[nf][0] = __expf(accS[nf][0] - mn0);
            accS[nf][1] = __expf(accS[nf][1] - mn0);
            accS[nf][2] = __expf(accS[nf][2] - mn1);
            accS[nf][3] = __expf(accS[nf][3] - mn1);
            s0 += accS[nf][0] + accS[nf][1];
            s1 += accS[nf][2] + accS[nf][3];
        }
        s0 += __shfl_xor_sync(0xffffffffu, s0, 1);
        s0 += __shfl_xor_sync(0xffffffffu, s0, 2);
        s1 += __shfl_xor_sync(0xffffffffu, s1, 1);
        s1 += __shfl_xor_sync(0xffffffffu, s1, 2);

        lrow[0] = lrow[0] * al0 + s0;
        lrow[1] = lrow[1] * al1 + s1;
        mrow[0] = mn0; mrow[1] = mn1;

#pragma unroll
        for (int nf = 0; nf < 8; nf++) {
            accO[nf][0] *= al0; accO[nf][1] *= al0;
            accO[nf][2] *= al1; accO[nf][3] *= al1;
        }

        // P -> fp16, warp-private rows of Ss
#pragma unroll
        for (int nf = 0; nf < 8; nf++) {
            __half2 p0 = __floats2half2_rn(accS[nf][0], accS[nf][1]);
            __half2 p1 = __floats2half2_rn(accS[nf][2], accS[nf][3]);
            Ss[r * AST + nf * 4 + c]       = *(unsigned*)&p0;
            Ss[(r + 8) * AST + nf * 4 + c] = *(unsigned*)&p1;
        }
        __syncwarp();  // warp-local P round-trip only

        // O += P @ V   (keys in 4 k16 chunks; Vt rows = dims)
#pragma unroll
        for (int k16 = 0; k16 < 4; k16++) {
            const int ku = k16 * 8;
            unsigned a[4];
            a[0] = Ss[r * AST + ku + c];
            a[1] = Ss[(r + 8) * AST + ku + c];
            a[2] = Ss[r * AST + ku + c + 4];
            a[3] = Ss[(r + 8) * AST + ku + c + 4];
#pragma unroll
            for (int nf = 0; nf < 8; nf++) {
                unsigned bf0, bf1;
                int vr = nf * 8 + lr;
                bf0 = Vb[vr * AST + ku + c];
                bf1 = Vb[vr * AST + ku + c + 4];
                mma16(accO[nf], a, bf0, bf1);
            }
        }
        __syncthreads();  // all warps done with buf before its next overwrite
    }

    // Normalize, write y fp16 [B,T,C]
    float inv0 = 1.0f / lrow[0], inv1 = 1.0f / lrow[1];
    size_t t0 = (size_t)b * TS + (size_t)qt * 128 + r;
#pragma unroll
    for (int nf = 0; nf < 8; nf++) {
        int c0 = nf * 8 + 2 * (lane & 3);
        *(__half2*)(yg + t0 * DM + h * 64 + c0) =
            __floats2half2_rn(accO[nf][0] * inv0, accO[nf][1] * inv0);
        *(__half2*)(yg + (t0 + 8) * DM + h * 64 + c0) =
            __floats2half2_rn(accO[nf][2] * inv1, accO[nf][3] * inv1);
    }
}

// ---------------------------------------------------------------------------
extern "C" void kernel_launch(void* const* d_in, const int* in_sizes, int n_in,
                              void* d_out, int out_size) {
    const float* x      = (const float*)d_in[0];
    const float* w_attn = (const float*)d_in[1];
    const float* b_attn = (const float*)d_in[2];
    const float* w_proj = (const float*)d_in[3];
    const float* b_proj = (const float*)d_in[4];
    float* out = (float*)d_out;

    __half *qp, *kp, *vp, *yp, *xh, *wah, *wph;
    cudaGetSymbolAddress((void**)&qp, g_q);
    cudaGetSymbolAddress((void**)&kp, g_k);
    cudaGetSymbolAddress((void**)&vp, g_v);
    cudaGetSymbolAddress((void**)&yp, g_y);
    cudaGetSymbolAddress((void**)&xh, g_xh);
    cudaGetSymbolAddress((void**)&wah, g_wah);
    cudaGetSymbolAddress((void**)&wph, g_wph);

    cudaFuncSetAttribute(gemm_h<1>, cudaFuncAttributeMaxDynamicSharedMemorySize,
                         GEMM_SMEM);
    cudaFuncSetAttribute(gemm_h<0>, cudaFuncAttributeMaxDynamicSharedMemorySize,
                         GEMM_SMEM);
    cudaFuncSetAttribute(attn_kernel, cudaFuncAttributeMaxDynamicSharedMemorySize,
                         ATTN_SMEM);

    // 0) convert inputs to fp16 (RN)
    f2h<<<ELEMS / 2 / 256, 256>>>((const float2*)x, (__half2*)xh, ELEMS / 2);
    f2h<<<3 * DM * DM / 2 / 256, 256>>>((const float2*)w_attn, (__half2*)wah,
                                        3 * DM * DM / 2);
    f2h<<<DM * DM / 2 / 256, 256>>>((const float2*)w_proj, (__half2*)wph,
                                    DM * DM / 2);

    // 1) QKV projection -> q/k [B,H,T,dk] (Q pre-scaled), v [B,H,dk,T]
    gemm_h<1><<<dim3(3 * DM / 128, MTOT / 128), 256, GEMM_SMEM>>>(
        xh, wah, b_attn, nullptr, qp, kp, vp, MTOT, 3 * DM, DM);

    // 2) Flash attention -> y fp16 [B,T,C]
    attn_kernel<<<dim3(TS / 128, NH, BB), 256, ATTN_SMEM>>>(qp, kp, vp, yp);

    // 3) Output projection -> d_out (fp32 + bias)
    gemm_h<0><<<dim3(DM / 128, MTOT / 128), 256, GEMM_SMEM>>>(
        yp, wph, b_proj, out, nullptr, nullptr, nullptr, MTOT, DM, DM);
}